// round 5
// baseline (speedup 1.0000x reference)
#include <cuda_runtime.h>
#include <math.h>

#define DOF 7
#define BATCH 16384
#define NTHREADS 128         // 4 warps per block, 32 elements/block
#define ACTION_RANGE 50.0f
#define MAX_VEL 20.0f
#define TSTEP 0.1f

struct Params {
    float w[DOF][3];
    float v[DOF][3];
    float wxv[DOF][3];
    float wdv[DOF];
    float Rm[DOF][9];     // trans_inv(Mlist[i]) rotation
    float pm[DOF][3];     // trans_inv(Mlist[i]) translation
    float Gd[DOF][6];
    float Mr[DOF + 1][9]; // Mlist rotations (FK)
    float Mp[DOF + 1][3]; // Mlist translations (FK)
};

__device__ Params g_params;

__device__ __forceinline__ void cross3(const float* a, const float* b, float* o) {
    o[0] = a[1] * b[2] - a[2] * b[1];
    o[1] = a[2] * b[0] - a[0] * b[2];
    o[2] = a[0] * b[1] - a[1] * b[0];
}

// ---------------------------------------------------------------------------
// Setup: parallel across 15 threads (8 frames + 7 joints).
// ---------------------------------------------------------------------------
__global__ void setup_kernel(const float* __restrict__ M_,
                             const float* __restrict__ A_,
                             const float* __restrict__ G_) {
    int t = threadIdx.x;
    Params* P = &g_params;
    if (t < 8) {
        int m = t;
        const float* M = M_ + m * 16;
        float a1[3], a2[3], p[3];
        for (int r = 0; r < 3; r++) { a1[r] = M[r * 4 + 0]; a2[r] = M[r * 4 + 1]; p[r] = M[r * 4 + 3]; }
        float n1 = sqrtf(a1[0] * a1[0] + a1[1] * a1[1] + a1[2] * a1[2]);
        float b1[3] = { a1[0] / n1, a1[1] / n1, a1[2] / n1 };
        float d = a2[0] * b1[0] + a2[1] * b1[1] + a2[2] * b1[2];
        float a2o[3] = { a2[0] - d * b1[0], a2[1] - d * b1[1], a2[2] - d * b1[2] };
        float n2 = sqrtf(a2o[0] * a2o[0] + a2o[1] * a2o[1] + a2o[2] * a2o[2]);
        float b2[3] = { a2o[0] / n2, a2o[1] / n2, a2o[2] / n2 };
        float b3[3]; cross3(b1, b2, b3);
        float R[9];
        for (int r = 0; r < 3; r++) { R[r * 3 + 0] = b1[r]; R[r * 3 + 1] = b2[r]; R[r * 3 + 2] = b3[r]; }
        for (int k = 0; k < 9; k++) P->Mr[m][k] = R[k];
        for (int r = 0; r < 3; r++) P->Mp[m][r] = p[r];
        if (m < DOF) {
            float Rt_[9];
            for (int r = 0; r < 3; r++)
                for (int c = 0; c < 3; c++) Rt_[r * 3 + c] = R[c * 3 + r];
            for (int k = 0; k < 9; k++) P->Rm[m][k] = Rt_[k];
            for (int r = 0; r < 3; r++)
                P->pm[m][r] = -(Rt_[r * 3 + 0] * p[0] + Rt_[r * 3 + 1] * p[1] + Rt_[r * 3 + 2] * p[2]);
        }
    } else if (t < 8 + DOF) {
        int j = t - 8;
        const float* a = A_ + j * 6;
        float nw = sqrtf(a[0] * a[0] + a[1] * a[1] + a[2] * a[2]);
        float w[3] = { a[0] / nw, a[1] / nw, a[2] / nw };
        float v[3] = { a[3], a[4], a[5] };
        for (int k = 0; k < 3; k++) { P->w[j][k] = w[k]; P->v[j][k] = v[k]; }
        cross3(w, v, P->wxv[j]);
        P->wdv[j] = w[0] * v[0] + w[1] * v[1] + w[2] * v[2];
        float g0 = fabsf(G_[j * 4 + 0]);
        float g1 = fabsf(G_[j * 4 + 1]);
        float g2 = fabsf(G_[j * 4 + 2]);
        float g3 = fabsf(G_[j * 4 + 3]);
        P->Gd[j][0] = g0; P->Gd[j][1] = g1; P->Gd[j][2] = g2;
        P->Gd[j][3] = g3; P->Gd[j][4] = g3; P->Gd[j][5] = g3;
    }
}

// Load one joint's adjoint (R, p) from the shared float4 buffer.
__device__ __forceinline__ void load_adj(const float4 (*abuf)[32], int lane, int i,
                                         float* R, float* p) {
    float4 c0 = abuf[3 * i + 0][lane];
    float4 c1 = abuf[3 * i + 1][lane];
    float4 c2 = abuf[3 * i + 2][lane];
    R[0] = c0.x; R[1] = c0.y; R[2] = c0.z; R[3] = c0.w;
    R[4] = c1.x; R[5] = c1.y; R[6] = c1.z; R[7] = c1.w;
    R[8] = c2.x; p[0] = c2.y; p[1] = c2.z; p[2] = c2.w;
}

// AdT @ V : out_w = R w_in ; out_v = p x out_w + R v_in   (safe if out==in)
__device__ __forceinline__ void adV_rp(const float* R, const float* p,
                                       const float* in, float* out) {
    float a0 = R[0] * in[0] + R[1] * in[1] + R[2] * in[2];
    float a1 = R[3] * in[0] + R[4] * in[1] + R[5] * in[2];
    float a2 = R[6] * in[0] + R[7] * in[1] + R[8] * in[2];
    float b0 = R[0] * in[3] + R[1] * in[4] + R[2] * in[5];
    float b1 = R[3] * in[3] + R[4] * in[4] + R[5] * in[5];
    float b2 = R[6] * in[3] + R[7] * in[4] + R[8] * in[5];
    out[0] = a0; out[1] = a1; out[2] = a2;
    out[3] = b0 + p[1] * a2 - p[2] * a1;
    out[4] = b1 + p[2] * a0 - p[0] * a2;
    out[5] = b2 + p[0] * a1 - p[1] * a0;
}

// AdT^T @ F : out_m = R^T (m + f x p) ; out_f = R^T f
__device__ __forceinline__ void adTF_rp(const float* R, const float* p,
                                        const float* in, float* out) {
    float m0 = in[0] + in[4] * p[2] - in[5] * p[1];
    float m1 = in[1] + in[5] * p[0] - in[3] * p[2];
    float m2 = in[2] + in[3] * p[1] - in[4] * p[0];
    out[0] = R[0] * m0 + R[3] * m1 + R[6] * m2;
    out[1] = R[1] * m0 + R[4] * m1 + R[7] * m2;
    out[2] = R[2] * m0 + R[5] * m1 + R[8] * m2;
    out[3] = R[0] * in[3] + R[3] * in[4] + R[6] * in[5];
    out[4] = R[1] * in[3] + R[4] * in[4] + R[7] * in[5];
    out[5] = R[2] * in[3] + R[5] * in[4] + R[8] * in[5];
}

__device__ __forceinline__ float dot6(const float* F, const float* w, const float* v) {
    return F[0] * w[0] + F[1] * w[1] + F[2] * w[2]
         + F[3] * v[0] + F[4] * v[1] + F[5] * v[2];
}

#define MTRI(i, j) Mtri[((i) * ((i) + 1)) / 2 + (j)]   // i >= j
// Exchange layout: [0..6] bias ; col j lower-tri entries start at colbase(j)
__device__ __forceinline__ constexpr int colbase(int j) {
    return (j == 0) ? 7 : (j == 1) ? 14 : (j == 2) ? 20 : (j == 3) ? 25
         : (j == 4) ? 29 : (j == 5) ? 32 : 34;
}

// Build adjoint for joint i from q_i, write (R,p) to shared.
__device__ __forceinline__ void build_adj(const Params& sp, float q, int i, int lane,
                                          float4 (*abuf)[32]) {
    float s, c;
    __sincosf(q, &s, &c);
    float th = -q, se = -s;
    const float* w = sp.w[i];
    const float* v = sp.v[i];
    float omc = 1.0f - c;
    float Re[9];
    Re[0] = c + omc * w[0] * w[0];
    Re[1] = se * (-w[2]) + omc * w[0] * w[1];
    Re[2] = se * ( w[1]) + omc * w[0] * w[2];
    Re[3] = se * ( w[2]) + omc * w[1] * w[0];
    Re[4] = c + omc * w[1] * w[1];
    Re[5] = se * (-w[0]) + omc * w[1] * w[2];
    Re[6] = se * (-w[1]) + omc * w[2] * w[0];
    Re[7] = se * ( w[0]) + omc * w[2] * w[1];
    Re[8] = c + omc * w[2] * w[2];
    float tms = th - se;
    float pe[3];
#pragma unroll
    for (int k = 0; k < 3; k++)
        pe[k] = th * v[k] + omc * sp.wxv[i][k] + tms * (w[k] * sp.wdv[i] - v[k]);
    const float* Rm = sp.Rm[i];
    float R[9];
#pragma unroll
    for (int r = 0; r < 3; r++)
#pragma unroll
        for (int cc = 0; cc < 3; cc++)
            R[r * 3 + cc] = Re[r * 3 + 0] * Rm[0 * 3 + cc]
                          + Re[r * 3 + 1] * Rm[1 * 3 + cc]
                          + Re[r * 3 + 2] * Rm[2 * 3 + cc];
    float p[3];
#pragma unroll
    for (int r = 0; r < 3; r++)
        p[r] = Re[r * 3 + 0] * sp.pm[i][0] + Re[r * 3 + 1] * sp.pm[i][1]
             + Re[r * 3 + 2] * sp.pm[i][2] + pe[r];
    abuf[3 * i + 0][lane] = make_float4(R[0], R[1], R[2], R[3]);
    abuf[3 * i + 1][lane] = make_float4(R[4], R[5], R[6], R[7]);
    abuf[3 * i + 2][lane] = make_float4(R[8], p[0], p[1], p[2]);
}

// Mass-matrix column J; vd scratch in tid-indexed shared, last vd in regs.
template<int J>
__device__ __forceinline__ void mass_col(const float4 (*abuf)[32], int lane, int tid,
                                         const Params& sp, float (*xch)[32],
                                         float (*scratch)[NTHREADS]) {
    float cur[6];
#pragma unroll
    for (int k = 0; k < 3; k++) { cur[k] = sp.w[J][k]; cur[3 + k] = sp.v[J][k]; }
#pragma unroll
    for (int i = J; i < DOF - 1; i++) {
#pragma unroll
        for (int k = 0; k < 6; k++) scratch[i * 6 + k][tid] = cur[k];
        float R[9], p[3];
        load_adj(abuf, lane, i + 1, R, p);
        adV_rp(R, p, cur, cur);
    }
    // cur == vd[6]
    float F[6];
#pragma unroll
    for (int k = 0; k < 6; k++) F[k] = sp.Gd[DOF - 1][k] * cur[k];
    xch[colbase(J) + (DOF - 1) - J][lane] = dot6(F, sp.w[DOF - 1], sp.v[DOF - 1]);
#pragma unroll
    for (int ii = DOF - 2; ii >= J; ii--) {
        float R[9], p[3];
        load_adj(abuf, lane, ii + 1, R, p);
        float X[6];
        adTF_rp(R, p, F, X);
#pragma unroll
        for (int k = 0; k < 6; k++) F[k] = X[k] + sp.Gd[ii][k] * scratch[ii * 6 + k][tid];
        xch[colbase(J) + ii - J][lane] = dot6(F, sp.w[ii], sp.v[ii]);
    }
}

// Bias inverse dynamics; fb scratch in tid-indexed shared, last fb in regs.
__device__ __forceinline__ void bias_calc(const float4 (*abuf)[32], int lane, int tid,
                                          const Params& sp, const float* dqc,
                                          const float* g, float (*xch)[32],
                                          float (*scratch)[NTHREADS]) {
    float fb_last[6];
    {
        float V[6] = { 0, 0, 0, 0, 0, 0 };
        float Vd[6] = { 0, 0, 0, -g[0], -g[1], -g[2] };
#pragma unroll
        for (int i = 0; i < DOF; i++) {
            float R[9], p[3];
            load_adj(abuf, lane, i, R, p);
            float t[6];
            adV_rp(R, p, V, t);
#pragma unroll
            for (int k = 0; k < 3; k++) {
                V[k]     = t[k]     + sp.w[i][k] * dqc[i];
                V[3 + k] = t[3 + k] + sp.v[i][k] * dqc[i];
            }
            float t2[6];
            adV_rp(R, p, Vd, t2);
            float aw[3], av1[3], av2[3];
            cross3(&V[0], sp.w[i], aw);
            cross3(&V[3], sp.w[i], av1);
            cross3(&V[0], sp.v[i], av2);
#pragma unroll
            for (int k = 0; k < 3; k++) {
                Vd[k]     = t2[k]     + aw[k] * dqc[i];
                Vd[3 + k] = t2[3 + k] + (av1[k] + av2[k]) * dqc[i];
            }
            float GV[6], GVd[6];
#pragma unroll
            for (int k = 0; k < 6; k++) {
                GV[k]  = sp.Gd[i][k] * V[k];
                GVd[k] = sp.Gd[i][k] * Vd[k];
            }
            float c1[3], c2[3], c3[3];
            cross3(&V[0], &GV[0], c1);
            cross3(&V[3], &GV[3], c2);
            cross3(&V[0], &GV[3], c3);
            float fbi[6];
#pragma unroll
            for (int k = 0; k < 3; k++) {
                fbi[k]     = GVd[k]     + c1[k] + c2[k];
                fbi[3 + k] = GVd[3 + k] + c3[k];
            }
            if (i < DOF - 1) {
#pragma unroll
                for (int k = 0; k < 6; k++) scratch[i * 6 + k][tid] = fbi[k];
            } else {
#pragma unroll
                for (int k = 0; k < 6; k++) fb_last[k] = fbi[k];
            }
        }
    }
    float F[6];
#pragma unroll
    for (int k = 0; k < 6; k++) F[k] = fb_last[k];
    xch[DOF - 1][lane] = dot6(F, sp.w[DOF - 1], sp.v[DOF - 1]);
#pragma unroll
    for (int ii = DOF - 2; ii >= 0; ii--) {
        float R[9], p[3];
        load_adj(abuf, lane, ii + 1, R, p);
        float X[6];
        adTF_rp(R, p, F, X);
#pragma unroll
        for (int k = 0; k < 6; k++) F[k] = X[k] + scratch[ii * 6 + k][tid];
        xch[ii][lane] = dot6(F, sp.w[ii], sp.v[ii]);
    }
}

// ---------------------------------------------------------------------------
// Main kernel: 4 warps per block share each 32-element group's work.
// ---------------------------------------------------------------------------
__global__ void __launch_bounds__(NTHREADS, 4)
arm_kernel(const float* __restrict__ state, const float* __restrict__ action,
           const float* __restrict__ gravity, float* __restrict__ out) {
    __shared__ Params sp;
    __shared__ float4 abuf[21][32];        // per-lane adjoints (R,p) x 7 joints
    __shared__ float xch[35][32];          // bias (7) + lower-tri mass (28)
    __shared__ float scratch[42][NTHREADS];// per-thread fb/vd scratch
    {
        const float* src = reinterpret_cast<const float*>(&g_params);
        float* dst = reinterpret_cast<float*>(&sp);
        for (int idx = threadIdx.x; idx < (int)(sizeof(Params) / 4); idx += NTHREADS)
            dst[idx] = src[idx];
    }
    __syncthreads();

    const int tid = threadIdx.x;
    const int lane = tid & 31;
    const int role = tid >> 5;                 // 0..3
    const int b = blockIdx.x * 32 + lane;

    float q0[DOF], dq0[DOF], tq[DOF], g[3];
#pragma unroll
    for (int i = 0; i < DOF; i++) {
        q0[i]  = state[b * 14 + i];
        dq0[i] = state[b * 14 + DOF + i];
        tq[i]  = action[b * DOF + i] * ACTION_RANGE;
    }
    g[0] = gravity[0]; g[1] = gravity[1]; g[2] = gravity[2];

    const float h = TSTEP;
    float qs[DOF], dqs[DOF], qc[DOF], dqc[DOF];
#pragma unroll
    for (int i = 0; i < DOF; i++) { qc[i] = q0[i]; dqc[i] = dq0[i]; qs[i] = 0.f; dqs[i] = 0.f; }

#pragma unroll 1
    for (int st = 0; st < 4; st++) {
        // ---- adjoint builds: role0:{0} role1:{1,2} role2:{3,4} role3:{5,6} ----
        if (role == 0) {
            build_adj(sp, qc[0], 0, lane, abuf);
        } else if (role == 1) {
            build_adj(sp, qc[1], 1, lane, abuf);
            build_adj(sp, qc[2], 2, lane, abuf);
        } else if (role == 2) {
            build_adj(sp, qc[3], 3, lane, abuf);
            build_adj(sp, qc[4], 4, lane, abuf);
        } else {
            build_adj(sp, qc[5], 5, lane, abuf);
            build_adj(sp, qc[6], 6, lane, abuf);
        }
        __syncthreads();

        // ---- role-split dynamics ----
        if (role == 0) {
            bias_calc(abuf, lane, tid, sp, dqc, g, xch, scratch);
        } else if (role == 1) {
            mass_col<0>(abuf, lane, tid, sp, xch, scratch);
            mass_col<4>(abuf, lane, tid, sp, xch, scratch);
        } else if (role == 2) {
            mass_col<1>(abuf, lane, tid, sp, xch, scratch);
            mass_col<3>(abuf, lane, tid, sp, xch, scratch);
        } else {
            mass_col<2>(abuf, lane, tid, sp, xch, scratch);
            mass_col<5>(abuf, lane, tid, sp, xch, scratch);
            mass_col<6>(abuf, lane, tid, sp, xch, scratch);
        }
        __syncthreads();

        // ---- gather ----
        float bias[DOF], Mtri[(DOF * (DOF + 1)) / 2];
#pragma unroll
        for (int i = 0; i < DOF; i++) bias[i] = xch[i][lane];
#pragma unroll
        for (int j = 0; j < DOF; j++)
#pragma unroll
            for (int i = j; i < DOF; i++)
                MTRI(i, j) = xch[colbase(j) + i - j][lane];

        // ---- LDL^T solve (duplicated; cheap) ----
        float x[DOF], invd[DOF];
#pragma unroll
        for (int i = 0; i < DOF; i++) x[i] = tq[i] - bias[i];
#pragma unroll
        for (int k = 0; k < DOF; k++) {
            float inv = __fdividef(1.0f, MTRI(k, k));
            invd[k] = inv;
            float fk[DOF];
#pragma unroll
            for (int i = k + 1; i < DOF; i++) fk[i] = MTRI(i, k) * inv;
#pragma unroll
            for (int i = k + 1; i < DOF; i++) {
                x[i] -= fk[i] * x[k];
#pragma unroll
                for (int jj = k + 1; jj <= i; jj++)
                    MTRI(i, jj) -= fk[i] * MTRI(jj, k);
            }
#pragma unroll
            for (int i = k + 1; i < DOF; i++) MTRI(i, k) = fk[i];
        }
#pragma unroll
        for (int i = 0; i < DOF; i++) x[i] *= invd[i];
#pragma unroll
        for (int i = DOF - 2; i >= 0; i--) {
            float s = x[i];
#pragma unroll
            for (int jj = i + 1; jj < DOF; jj++) s -= MTRI(jj, i) * x[jj];
            x[i] = s;
        }

        // ---- RK bookkeeping ----
        float wk = (st == 1 || st == 2) ? 2.0f : 1.0f;
        float cc = (st == 2) ? 1.0f : 0.5f;
#pragma unroll
        for (int i = 0; i < DOF; i++) {
            qs[i]  += wk * dqc[i];
            dqs[i] += wk * x[i];
            qc[i]  = q0[i]  + cc * h * dqc[i];
            dqc[i] = dq0[i] + cc * h * x[i];
        }
    }

    const float PI = 3.14159265358979323846f;
    const float TWO_PI = 6.28318530717958647692f;
    float qn[DOF];
#pragma unroll
    for (int i = 0; i < DOF; i++) {
        float qv = q0[i] + (h / 6.0f) * qs[i];
        float t = fmodf(qv + PI, TWO_PI);
        if (t < 0.0f) t += TWO_PI;
        qn[i] = t - PI;
    }
    if (role == 0) {
#pragma unroll
        for (int i = 0; i < DOF; i++) out[b * 14 + i] = qn[i];
        return;
    }
    if (role == 1) {
#pragma unroll
        for (int i = 0; i < DOF; i++) {
            float dv = dq0[i] + (h / 6.0f) * dqs[i];
            dv = fminf(fmaxf(dv, -MAX_VEL), MAX_VEL);
            out[b * 14 + DOF + i] = dv;
        }
        return;
    }

    // ---- FK (roles 2,3): row (role-2) of T; ee component = role-2 ----
    const int fkrow = role - 2;
    float TRr[3] = { fkrow == 0 ? 1.f : 0.f, fkrow == 0 ? 0.f : 1.f, 0.f };
    float Tpr = 0.f;
#pragma unroll
    for (int i = 0; i < DOF; i++) {
        float s, c;
        __sincosf(qn[i], &s, &c);
        const float* w = sp.w[i];
        const float* v = sp.v[i];
        float omc = 1.0f - c;
        float Re[9];
        Re[0] = c + omc * w[0] * w[0];
        Re[1] = s * (-w[2]) + omc * w[0] * w[1];
        Re[2] = s * ( w[1]) + omc * w[0] * w[2];
        Re[3] = s * ( w[2]) + omc * w[1] * w[0];
        Re[4] = c + omc * w[1] * w[1];
        Re[5] = s * (-w[0]) + omc * w[1] * w[2];
        Re[6] = s * (-w[1]) + omc * w[2] * w[0];
        Re[7] = s * ( w[0]) + omc * w[2] * w[1];
        Re[8] = c + omc * w[2] * w[2];
        float th = qn[i];
        float tms = th - s;
        float pe[3];
#pragma unroll
        for (int k = 0; k < 3; k++)
            pe[k] = th * v[k] + omc * sp.wxv[i][k] + tms * (w[k] * sp.wdv[i] - v[k]);
        const float* Mr = sp.Mr[i];
        const float* Mp = sp.Mp[i];
        float Tm[3];
#pragma unroll
        for (int cc2 = 0; cc2 < 3; cc2++)
            Tm[cc2] = TRr[0] * Mr[0 * 3 + cc2] + TRr[1] * Mr[1 * 3 + cc2] + TRr[2] * Mr[2 * 3 + cc2];
        Tpr += TRr[0] * Mp[0] + TRr[1] * Mp[1] + TRr[2] * Mp[2]
             + Tm[0] * pe[0] + Tm[1] * pe[1] + Tm[2] * pe[2];
        float nTR[3];
#pragma unroll
        for (int cc2 = 0; cc2 < 3; cc2++)
            nTR[cc2] = Tm[0] * Re[0 * 3 + cc2] + Tm[1] * Re[1 * 3 + cc2] + Tm[2] * Re[2 * 3 + cc2];
        TRr[0] = nTR[0]; TRr[1] = nTR[1]; TRr[2] = nTR[2];
    }
    const float* Mp7 = sp.Mp[DOF];
    float e = TRr[0] * Mp7[0] + TRr[1] * Mp7[1] + TRr[2] * Mp7[2] + Tpr;
    out[BATCH * 14 + b * 2 + fkrow] = e;
}

extern "C" void kernel_launch(void* const* d_in, const int* in_sizes, int n_in,
                              void* d_out, int out_size) {
    const float* state   = (const float*)d_in[0];
    const float* action  = (const float*)d_in[1];
    const float* M_      = (const float*)d_in[2];
    const float* A_      = (const float*)d_in[3];
    const float* G_      = (const float*)d_in[4];
    const float* gravity = (const float*)d_in[5];
    float* out = (float*)d_out;

    setup_kernel<<<1, 32>>>(M_, A_, G_);
    arm_kernel<<<BATCH / 32, NTHREADS>>>(state, action, gravity, out);
}

// round 6
// speedup vs baseline: 1.2386x; 1.2386x over previous
#include <cuda_runtime.h>
#include <math.h>

#define DOF 7
#define BATCH 16384
#define NTHREADS 64          // 2 warps per block, 32 elements/block
#define ACTION_RANGE 50.0f
#define MAX_VEL 20.0f
#define TSTEP 0.1f

struct Params {
    float w[DOF][3];
    float v[DOF][3];
    float wxv[DOF][3];
    float wdv[DOF];
    float Rm[DOF][9];     // trans_inv(Mlist[i]) rotation
    float pm[DOF][3];     // trans_inv(Mlist[i]) translation
    float Gd[DOF][6];
    float Mr[DOF + 1][9]; // Mlist rotations (FK)
    float Mp[DOF + 1][3]; // Mlist translations (FK)
};

__device__ __forceinline__ void cross3(const float* a, const float* b, float* o) {
    o[0] = a[1] * b[2] - a[2] * b[1];
    o[1] = a[2] * b[0] - a[0] * b[2];
    o[2] = a[0] * b[1] - a[1] * b[0];
}

// Load one joint's adjoint (R, p) from the shared float4 buffer.
__device__ __forceinline__ void load_adj(const float4 (*abuf)[32], int lane, int i,
                                         float* R, float* p) {
    float4 c0 = abuf[3 * i + 0][lane];
    float4 c1 = abuf[3 * i + 1][lane];
    float4 c2 = abuf[3 * i + 2][lane];
    R[0] = c0.x; R[1] = c0.y; R[2] = c0.z; R[3] = c0.w;
    R[4] = c1.x; R[5] = c1.y; R[6] = c1.z; R[7] = c1.w;
    R[8] = c2.x; p[0] = c2.y; p[1] = c2.z; p[2] = c2.w;
}

// AdT @ V : out_w = R w_in ; out_v = p x out_w + R v_in
__device__ __forceinline__ void adV_rp(const float* R, const float* p,
                                       const float* in, float* out) {
    float a0 = R[0] * in[0] + R[1] * in[1] + R[2] * in[2];
    float a1 = R[3] * in[0] + R[4] * in[1] + R[5] * in[2];
    float a2 = R[6] * in[0] + R[7] * in[1] + R[8] * in[2];
    float b0 = R[0] * in[3] + R[1] * in[4] + R[2] * in[5];
    float b1 = R[3] * in[3] + R[4] * in[4] + R[5] * in[5];
    float b2 = R[6] * in[3] + R[7] * in[4] + R[8] * in[5];
    out[0] = a0; out[1] = a1; out[2] = a2;
    out[3] = b0 + p[1] * a2 - p[2] * a1;
    out[4] = b1 + p[2] * a0 - p[0] * a2;
    out[5] = b2 + p[0] * a1 - p[1] * a0;
}

// AdT^T @ F : out_m = R^T (m + f x p) ; out_f = R^T f
__device__ __forceinline__ void adTF_rp(const float* R, const float* p,
                                        const float* in, float* out) {
    float m0 = in[0] + in[4] * p[2] - in[5] * p[1];
    float m1 = in[1] + in[5] * p[0] - in[3] * p[2];
    float m2 = in[2] + in[3] * p[1] - in[4] * p[0];
    out[0] = R[0] * m0 + R[3] * m1 + R[6] * m2;
    out[1] = R[1] * m0 + R[4] * m1 + R[7] * m2;
    out[2] = R[2] * m0 + R[5] * m1 + R[8] * m2;
    out[3] = R[0] * in[3] + R[3] * in[4] + R[6] * in[5];
    out[4] = R[1] * in[3] + R[4] * in[4] + R[7] * in[5];
    out[5] = R[2] * in[3] + R[5] * in[4] + R[8] * in[5];
}

__device__ __forceinline__ float dot6(const float* F, const float* w, const float* v) {
    return F[0] * w[0] + F[1] * w[1] + F[2] * w[2]
         + F[3] * v[0] + F[4] * v[1] + F[5] * v[2];
}

#define MTRI(i, j) Mtri[((i) * ((i) + 1)) / 2 + (j)]   // i >= j
// Exchange layout: [0..6] bias ; col j lower-tri entries start at colbase(j)
__device__ __forceinline__ constexpr int colbase(int j) {
    return (j == 0) ? 7 : (j == 1) ? 14 : (j == 2) ? 20 : (j == 3) ? 25
         : (j == 4) ? 29 : (j == 5) ? 32 : 34;
}

// Build adjoint for joint i from q_i, write (R,p) to shared.
__device__ __forceinline__ void build_adj(const Params& sp, float q, int i, int lane,
                                          float4 (*abuf)[32]) {
    float s, c;
    __sincosf(q, &s, &c);
    float th = -q, se = -s;
    const float* w = sp.w[i];
    const float* v = sp.v[i];
    float omc = 1.0f - c;
    float Re[9];
    Re[0] = c + omc * w[0] * w[0];
    Re[1] = se * (-w[2]) + omc * w[0] * w[1];
    Re[2] = se * ( w[1]) + omc * w[0] * w[2];
    Re[3] = se * ( w[2]) + omc * w[1] * w[0];
    Re[4] = c + omc * w[1] * w[1];
    Re[5] = se * (-w[0]) + omc * w[1] * w[2];
    Re[6] = se * (-w[1]) + omc * w[2] * w[0];
    Re[7] = se * ( w[0]) + omc * w[2] * w[1];
    Re[8] = c + omc * w[2] * w[2];
    float tms = th - se;
    float pe[3];
#pragma unroll
    for (int k = 0; k < 3; k++)
        pe[k] = th * v[k] + omc * sp.wxv[i][k] + tms * (w[k] * sp.wdv[i] - v[k]);
    const float* Rm = sp.Rm[i];
    float R[9];
#pragma unroll
    for (int r = 0; r < 3; r++)
#pragma unroll
        for (int cc = 0; cc < 3; cc++)
            R[r * 3 + cc] = Re[r * 3 + 0] * Rm[0 * 3 + cc]
                          + Re[r * 3 + 1] * Rm[1 * 3 + cc]
                          + Re[r * 3 + 2] * Rm[2 * 3 + cc];
    float p[3];
#pragma unroll
    for (int r = 0; r < 3; r++)
        p[r] = Re[r * 3 + 0] * sp.pm[i][0] + Re[r * 3 + 1] * sp.pm[i][1]
             + Re[r * 3 + 2] * sp.pm[i][2] + pe[r];
    abuf[3 * i + 0][lane] = make_float4(R[0], R[1], R[2], R[3]);
    abuf[3 * i + 1][lane] = make_float4(R[4], R[5], R[6], R[7]);
    abuf[3 * i + 2][lane] = make_float4(R[8], p[0], p[1], p[2]);
}

// Mass-matrix column J (lower-triangle rows J..6), adjoints read from shared.
template<int J>
__device__ __forceinline__ void mass_col(const float4 (*abuf)[32], int lane,
                                         const Params& sp, float (*xch)[32]) {
    float vd[DOF][6];
#pragma unroll
    for (int k = 0; k < 3; k++) { vd[J][k] = sp.w[J][k]; vd[J][3 + k] = sp.v[J][k]; }
#pragma unroll
    for (int i = J + 1; i < DOF; i++) {
        float R[9], p[3];
        load_adj(abuf, lane, i, R, p);
        adV_rp(R, p, vd[i - 1], vd[i]);
    }
    float F[6];
#pragma unroll
    for (int k = 0; k < 6; k++) F[k] = sp.Gd[DOF - 1][k] * vd[DOF - 1][k];
    xch[colbase(J) + (DOF - 1) - J][lane] = dot6(F, sp.w[DOF - 1], sp.v[DOF - 1]);
#pragma unroll
    for (int ii = DOF - 2; ii >= J; ii--) {
        float R[9], p[3];
        load_adj(abuf, lane, ii + 1, R, p);
        float X[6];
        adTF_rp(R, p, F, X);
#pragma unroll
        for (int k = 0; k < 6; k++) F[k] = X[k] + sp.Gd[ii][k] * vd[ii][k];
        xch[colbase(J) + ii - J][lane] = dot6(F, sp.w[ii], sp.v[ii]);
    }
}

// Bias inverse dynamics (ddq=0, gravity + velocity), adjoints from shared.
__device__ __forceinline__ void bias_calc(const float4 (*abuf)[32], int lane,
                                          const Params& sp, const float* dqc,
                                          const float* g, float (*xch)[32]) {
    float fb[DOF][6];
    {
        float V[6] = { 0, 0, 0, 0, 0, 0 };
        float Vd[6] = { 0, 0, 0, -g[0], -g[1], -g[2] };
#pragma unroll
        for (int i = 0; i < DOF; i++) {
            float R[9], p[3];
            load_adj(abuf, lane, i, R, p);
            float t[6];
            adV_rp(R, p, V, t);
#pragma unroll
            for (int k = 0; k < 3; k++) {
                V[k]     = t[k]     + sp.w[i][k] * dqc[i];
                V[3 + k] = t[3 + k] + sp.v[i][k] * dqc[i];
            }
            float t2[6];
            adV_rp(R, p, Vd, t2);
            float aw[3], av1[3], av2[3];
            cross3(&V[0], sp.w[i], aw);
            cross3(&V[3], sp.w[i], av1);
            cross3(&V[0], sp.v[i], av2);
#pragma unroll
            for (int k = 0; k < 3; k++) {
                Vd[k]     = t2[k]     + aw[k] * dqc[i];
                Vd[3 + k] = t2[3 + k] + (av1[k] + av2[k]) * dqc[i];
            }
            float GV[6], GVd[6];
#pragma unroll
            for (int k = 0; k < 6; k++) {
                GV[k]  = sp.Gd[i][k] * V[k];
                GVd[k] = sp.Gd[i][k] * Vd[k];
            }
            float c1[3], c2[3], c3[3];
            cross3(&V[0], &GV[0], c1);
            cross3(&V[3], &GV[3], c2);
            cross3(&V[0], &GV[3], c3);
#pragma unroll
            for (int k = 0; k < 3; k++) {
                fb[i][k]     = GVd[k]     + c1[k] + c2[k];
                fb[i][3 + k] = GVd[3 + k] + c3[k];
            }
        }
    }
    float F[6];
#pragma unroll
    for (int k = 0; k < 6; k++) F[k] = fb[DOF - 1][k];
    xch[DOF - 1][lane] = dot6(F, sp.w[DOF - 1], sp.v[DOF - 1]);
#pragma unroll
    for (int ii = DOF - 2; ii >= 0; ii--) {
        float R[9], p[3];
        load_adj(abuf, lane, ii + 1, R, p);
        float X[6];
        adTF_rp(R, p, F, X);
#pragma unroll
        for (int k = 0; k < 6; k++) F[k] = X[k] + fb[ii][k];
        xch[ii][lane] = dot6(F, sp.w[ii], sp.v[ii]);
    }
}

// ---------------------------------------------------------------------------
// Single fused kernel: per-block setup + 2-warp role-split dynamics.
// ---------------------------------------------------------------------------
__global__ void __launch_bounds__(NTHREADS)
arm_kernel(const float* __restrict__ state, const float* __restrict__ action,
           const float* __restrict__ M_, const float* __restrict__ A_,
           const float* __restrict__ G_, const float* __restrict__ gravity,
           float* __restrict__ out) {
    __shared__ Params sp;
    __shared__ float4 abuf[21][32];   // per-lane adjoints (R,p) x 7 joints
    __shared__ float xch[35][32];     // bias (7) + lower-tri mass (28)

    // ---- per-block setup (threads 0..14), replaces the setup kernel ----
    {
        int t = threadIdx.x;
        if (t < 8) {
            int m = t;
            const float* M = M_ + m * 16;
            float a1[3], a2[3], p[3];
#pragma unroll
            for (int r = 0; r < 3; r++) { a1[r] = M[r * 4 + 0]; a2[r] = M[r * 4 + 1]; p[r] = M[r * 4 + 3]; }
            float n1 = sqrtf(a1[0] * a1[0] + a1[1] * a1[1] + a1[2] * a1[2]);
            float b1[3] = { a1[0] / n1, a1[1] / n1, a1[2] / n1 };
            float d = a2[0] * b1[0] + a2[1] * b1[1] + a2[2] * b1[2];
            float a2o[3] = { a2[0] - d * b1[0], a2[1] - d * b1[1], a2[2] - d * b1[2] };
            float n2 = sqrtf(a2o[0] * a2o[0] + a2o[1] * a2o[1] + a2o[2] * a2o[2]);
            float b2[3] = { a2o[0] / n2, a2o[1] / n2, a2o[2] / n2 };
            float b3[3]; cross3(b1, b2, b3);
            float R[9];
#pragma unroll
            for (int r = 0; r < 3; r++) { R[r * 3 + 0] = b1[r]; R[r * 3 + 1] = b2[r]; R[r * 3 + 2] = b3[r]; }
#pragma unroll
            for (int k = 0; k < 9; k++) sp.Mr[m][k] = R[k];
#pragma unroll
            for (int r = 0; r < 3; r++) sp.Mp[m][r] = p[r];
            if (m < DOF) {
                float Rt_[9];
#pragma unroll
                for (int r = 0; r < 3; r++)
#pragma unroll
                    for (int c = 0; c < 3; c++) Rt_[r * 3 + c] = R[c * 3 + r];
#pragma unroll
                for (int k = 0; k < 9; k++) sp.Rm[m][k] = Rt_[k];
#pragma unroll
                for (int r = 0; r < 3; r++)
                    sp.pm[m][r] = -(Rt_[r * 3 + 0] * p[0] + Rt_[r * 3 + 1] * p[1] + Rt_[r * 3 + 2] * p[2]);
            }
        } else if (t < 8 + DOF) {
            int j = t - 8;
            const float* a = A_ + j * 6;
            float nw = sqrtf(a[0] * a[0] + a[1] * a[1] + a[2] * a[2]);
            float w[3] = { a[0] / nw, a[1] / nw, a[2] / nw };
            float v[3] = { a[3], a[4], a[5] };
#pragma unroll
            for (int k = 0; k < 3; k++) { sp.w[j][k] = w[k]; sp.v[j][k] = v[k]; }
            float wxv[3]; cross3(w, v, wxv);
#pragma unroll
            for (int k = 0; k < 3; k++) sp.wxv[j][k] = wxv[k];
            sp.wdv[j] = w[0] * v[0] + w[1] * v[1] + w[2] * v[2];
            float g0 = fabsf(G_[j * 4 + 0]);
            float g1 = fabsf(G_[j * 4 + 1]);
            float g2 = fabsf(G_[j * 4 + 2]);
            float g3 = fabsf(G_[j * 4 + 3]);
            sp.Gd[j][0] = g0; sp.Gd[j][1] = g1; sp.Gd[j][2] = g2;
            sp.Gd[j][3] = g3; sp.Gd[j][4] = g3; sp.Gd[j][5] = g3;
        }
    }
    __syncthreads();

    const int lane = threadIdx.x & 31;
    const int role = threadIdx.x >> 5;
    const int b = blockIdx.x * 32 + lane;

    float q0[DOF], dq0[DOF], tq[DOF], g[3];
#pragma unroll
    for (int i = 0; i < DOF; i++) {
        q0[i]  = state[b * 14 + i];
        dq0[i] = state[b * 14 + DOF + i];
        tq[i]  = action[b * DOF + i] * ACTION_RANGE;
    }
    g[0] = gravity[0]; g[1] = gravity[1]; g[2] = gravity[2];

    const float h = TSTEP;
    float qs[DOF], dqs[DOF], qc[DOF], dqc[DOF];
#pragma unroll
    for (int i = 0; i < DOF; i++) { qc[i] = q0[i]; dqc[i] = dq0[i]; qs[i] = 0.f; dqs[i] = 0.f; }

#pragma unroll 1
    for (int st = 0; st < 4; st++) {
        // ---- build adjoints (split: role0 joints 0-2, role1 joints 3-6) ----
        if (role == 0) {
            build_adj(sp, qc[0], 0, lane, abuf);
            build_adj(sp, qc[1], 1, lane, abuf);
            build_adj(sp, qc[2], 2, lane, abuf);
        } else {
            build_adj(sp, qc[3], 3, lane, abuf);
            build_adj(sp, qc[4], 4, lane, abuf);
            build_adj(sp, qc[5], 5, lane, abuf);
            build_adj(sp, qc[6], 6, lane, abuf);
        }
        __syncthreads();

        // ---- role-split dynamics ----
        if (role == 0) {
            bias_calc(abuf, lane, sp, dqc, g, xch);
            mass_col<4>(abuf, lane, sp, xch);
            mass_col<5>(abuf, lane, sp, xch);
            mass_col<6>(abuf, lane, sp, xch);
        } else {
            mass_col<0>(abuf, lane, sp, xch);
            mass_col<1>(abuf, lane, sp, xch);
            mass_col<2>(abuf, lane, sp, xch);
            mass_col<3>(abuf, lane, sp, xch);
        }
        __syncthreads();

        // ---- gather ----
        float bias[DOF], Mtri[(DOF * (DOF + 1)) / 2];
#pragma unroll
        for (int i = 0; i < DOF; i++) bias[i] = xch[i][lane];
#pragma unroll
        for (int j = 0; j < DOF; j++)
#pragma unroll
            for (int i = j; i < DOF; i++)
                MTRI(i, j) = xch[colbase(j) + i - j][lane];

        // ---- LDL^T solve (duplicated; cheap) ----
        float x[DOF], invd[DOF];
#pragma unroll
        for (int i = 0; i < DOF; i++) x[i] = tq[i] - bias[i];
#pragma unroll
        for (int k = 0; k < DOF; k++) {
            float inv = __fdividef(1.0f, MTRI(k, k));
            invd[k] = inv;
            float fk[DOF];
#pragma unroll
            for (int i = k + 1; i < DOF; i++) fk[i] = MTRI(i, k) * inv;
#pragma unroll
            for (int i = k + 1; i < DOF; i++) {
                x[i] -= fk[i] * x[k];
#pragma unroll
                for (int jj = k + 1; jj <= i; jj++)
                    MTRI(i, jj) -= fk[i] * MTRI(jj, k);
            }
#pragma unroll
            for (int i = k + 1; i < DOF; i++) MTRI(i, k) = fk[i];
        }
#pragma unroll
        for (int i = 0; i < DOF; i++) x[i] *= invd[i];
#pragma unroll
        for (int i = DOF - 2; i >= 0; i--) {
            float s = x[i];
#pragma unroll
            for (int jj = i + 1; jj < DOF; jj++) s -= MTRI(jj, i) * x[jj];
            x[i] = s;
        }

        // ---- RK bookkeeping ----
        float wk = (st == 1 || st == 2) ? 2.0f : 1.0f;
        float cc = (st == 2) ? 1.0f : 0.5f;
#pragma unroll
        for (int i = 0; i < DOF; i++) {
            qs[i]  += wk * dqc[i];
            dqs[i] += wk * x[i];
            qc[i]  = q0[i]  + cc * h * dqc[i];
            dqc[i] = dq0[i] + cc * h * x[i];
        }
    }

    const float PI = 3.14159265358979323846f;
    const float TWO_PI = 6.28318530717958647692f;
    float qn[DOF];
#pragma unroll
    for (int i = 0; i < DOF; i++) {
        float qv = q0[i] + (h / 6.0f) * qs[i];
        // qv in (-2pi, 2pi): branch-free wrap matching fmod semantics
        float t = qv;
        if (qv >= PI) t = qv - TWO_PI;
        else if (qv < -PI) t = qv + TWO_PI;
        qn[i] = t;
        if (role == 0) {
            out[b * 14 + i] = qn[i];
        } else {
            float dv = dq0[i] + (h / 6.0f) * dqs[i];
            dv = fminf(fmaxf(dv, -MAX_VEL), MAX_VEL);
            out[b * 14 + DOF + i] = dv;
        }
    }

    // ---- FK: row `role` of T propagates independently; ee component = role ----
    float TRr[3] = { role == 0 ? 1.f : 0.f, role == 0 ? 0.f : 1.f, 0.f };
    float Tpr = 0.f;
#pragma unroll
    for (int i = 0; i < DOF; i++) {
        float s, c;
        __sincosf(qn[i], &s, &c);
        const float* w = sp.w[i];
        const float* v = sp.v[i];
        float omc = 1.0f - c;
        float Re[9];
        Re[0] = c + omc * w[0] * w[0];
        Re[1] = s * (-w[2]) + omc * w[0] * w[1];
        Re[2] = s * ( w[1]) + omc * w[0] * w[2];
        Re[3] = s * ( w[2]) + omc * w[1] * w[0];
        Re[4] = c + omc * w[1] * w[1];
        Re[5] = s * (-w[0]) + omc * w[1] * w[2];
        Re[6] = s * (-w[1]) + omc * w[2] * w[0];
        Re[7] = s * ( w[0]) + omc * w[2] * w[1];
        Re[8] = c + omc * w[2] * w[2];
        float th = qn[i];
        float tms = th - s;
        float pe[3];
#pragma unroll
        for (int k = 0; k < 3; k++)
            pe[k] = th * v[k] + omc * sp.wxv[i][k] + tms * (w[k] * sp.wdv[i] - v[k]);
        const float* Mr = sp.Mr[i];
        const float* Mp = sp.Mp[i];
        float Tm[3];
#pragma unroll
        for (int cc2 = 0; cc2 < 3; cc2++)
            Tm[cc2] = TRr[0] * Mr[0 * 3 + cc2] + TRr[1] * Mr[1 * 3 + cc2] + TRr[2] * Mr[2 * 3 + cc2];
        Tpr += TRr[0] * Mp[0] + TRr[1] * Mp[1] + TRr[2] * Mp[2]
             + Tm[0] * pe[0] + Tm[1] * pe[1] + Tm[2] * pe[2];
        float nTR[3];
#pragma unroll
        for (int cc2 = 0; cc2 < 3; cc2++)
            nTR[cc2] = Tm[0] * Re[0 * 3 + cc2] + Tm[1] * Re[1 * 3 + cc2] + Tm[2] * Re[2 * 3 + cc2];
        TRr[0] = nTR[0]; TRr[1] = nTR[1]; TRr[2] = nTR[2];
    }
    const float* Mp7 = sp.Mp[DOF];
    float e = TRr[0] * Mp7[0] + TRr[1] * Mp7[1] + TRr[2] * Mp7[2] + Tpr;
    out[BATCH * 14 + b * 2 + role] = e;
}

extern "C" void kernel_launch(void* const* d_in, const int* in_sizes, int n_in,
                              void* d_out, int out_size) {
    const float* state   = (const float*)d_in[0];
    const float* action  = (const float*)d_in[1];
    const float* M_      = (const float*)d_in[2];
    const float* A_      = (const float*)d_in[3];
    const float* G_      = (const float*)d_in[4];
    const float* gravity = (const float*)d_in[5];
    float* out = (float*)d_out;

    arm_kernel<<<BATCH / 32, NTHREADS>>>(state, action, M_, A_, G_, gravity, out);
}